// round 16
// baseline (speedup 1.0000x reference)
#include <cuda_runtime.h>
#include <math.h>

#define BATCH 4
#define NTOK  2048
#define DMODEL 1024
#define HEADS 16
#define DH    64
#define INNER 1024
#define SCALE 0.125f                 /* 64^-0.5 */
#define CLOG2E 0.1803368801111f      /* SCALE * log2(e) */
#define TWO_C  0.3606737602222f      /* 2 * SCALE * log2(e) */

typedef unsigned long long u64;

__device__ __forceinline__ u64 pack2(float x) {
    u64 r; asm("mov.b64 %0, {%1, %1};" : "=l"(r) : "f"(x)); return r;
}
__device__ __forceinline__ float2 unpack2(u64 a) {
    float2 f; asm("mov.b64 {%0, %1}, %2;" : "=f"(f.x), "=f"(f.y) : "l"(a)); return f;
}
__device__ __forceinline__ void ffma2(u64 &d, u64 a, u64 b) {
    asm("fma.rn.f32x2 %0, %1, %2, %0;" : "+l"(d) : "l"(a), "l"(b));
}

// Scratch (allocation-free rule: __device__ globals)
__device__ float g_q[BATCH * NTOK * INNER];
__device__ float g_v[BATCH * NTOK * INNER];
__device__ float g_ao[BATCH * NTOK * INNER];
__device__ float g_norm[BATCH * HEADS * NTOK];   // ‖q‖² * SCALE * log2e

// ---------------------------------------------------------------------------
// SGEMM (f32x2, BK=8, double-buffered, dual-output) — R14/R15-proven, frozen.
// ---------------------------------------------------------------------------
__global__ __launch_bounds__(256, 2) void sgemm_dual(
    const float* __restrict__ A,
    const float* __restrict__ W0, const float* __restrict__ b0, float* __restrict__ C0,
    const float* __restrict__ W1, const float* __restrict__ b1, float* __restrict__ C1,
    float* __restrict__ nrm,
    int M, int N, int K)
{
    __shared__ float As[2][8][128];
    __shared__ float Bs[2][8][128];

    const int tid = threadIdx.x;
    const int set = blockIdx.x >> 3;
    const int bn = (blockIdx.x & 7) * 128;
    const int bm = blockIdx.y * 128;
    const int tx = tid & 15;
    const int ty = tid >> 4;

    const float* W    = set ? W1 : W0;
    const float* bias = set ? b1 : b0;
    float*       C    = set ? C1 : C0;

    const int arow = tid >> 1;
    const int acol = (tid & 1) * 4;
    const int brow = tid >> 5;
    const int bcol = (tid & 31) * 4;

    const float* Ap = A + (size_t)(bm + arow) * K + acol;
    const float* Wp = W + (size_t)brow * N + bn + bcol;

    u64 acc[8][4];
    #pragma unroll
    for (int i = 0; i < 8; i++)
        #pragma unroll
        for (int j = 0; j < 4; j++) acc[i][j] = 0ull;

    {
        float4 a4 = *(const float4*)Ap;
        As[0][acol + 0][arow] = a4.x;
        As[0][acol + 1][arow] = a4.y;
        As[0][acol + 2][arow] = a4.z;
        As[0][acol + 3][arow] = a4.w;
        *(float4*)&Bs[0][brow][bcol] = *(const float4*)Wp;
    }
    __syncthreads();

    const int nst = K >> 3;
    for (int s = 0; s < nst; s++) {
        const int cur = s & 1;
        float4 na, nb;
        const bool more = (s + 1 < nst);
        if (more) {
            na = *(const float4*)(Ap + (s + 1) * 8);
            nb = *(const float4*)(Wp + (size_t)(s + 1) * 8 * N);
        }

        #pragma unroll
        for (int kk = 0; kk < 8; kk++) {
            float4 a0 = *(const float4*)&As[cur][kk][ty * 8];
            float4 a1 = *(const float4*)&As[cur][kk][ty * 8 + 4];
            alignas(16) u64 b2[4];
            *(float4*)&b2[0] = *(const float4*)&Bs[cur][kk][tx * 4];
            *(float4*)&b2[2] = *(const float4*)&Bs[cur][kk][64 + tx * 4];
            u64 ad[8];
            ad[0] = pack2(a0.x); ad[1] = pack2(a0.y);
            ad[2] = pack2(a0.z); ad[3] = pack2(a0.w);
            ad[4] = pack2(a1.x); ad[5] = pack2(a1.y);
            ad[6] = pack2(a1.z); ad[7] = pack2(a1.w);
            #pragma unroll
            for (int i = 0; i < 8; i++)
                #pragma unroll
                for (int j = 0; j < 4; j++)
                    ffma2(acc[i][j], ad[i], b2[j]);
        }

        if (more) {
            const int nxt = cur ^ 1;
            As[nxt][acol + 0][arow] = na.x;
            As[nxt][acol + 1][arow] = na.y;
            As[nxt][acol + 2][arow] = na.z;
            As[nxt][acol + 3][arow] = na.w;
            *(float4*)&Bs[nxt][brow][bcol] = nb;
            __syncthreads();
        }
    }

    float4 bb0 = *(const float4*)(bias + bn + tx * 4);
    float4 bb1 = *(const float4*)(bias + bn + 64 + tx * 4);

    float ns0[8], ns1[8];

    #pragma unroll
    for (int i = 0; i < 8; i++) {
        float* Cp = C + (size_t)(bm + ty * 8 + i) * N + bn;
        float2 p0 = unpack2(acc[i][0]), p1 = unpack2(acc[i][1]);
        float2 p2 = unpack2(acc[i][2]), p3 = unpack2(acc[i][3]);
        float4 o0 = make_float4(p0.x + bb0.x, p0.y + bb0.y, p1.x + bb0.z, p1.y + bb0.w);
        float4 o1 = make_float4(p2.x + bb1.x, p2.y + bb1.y, p3.x + bb1.z, p3.y + bb1.w);
        *(float4*)(Cp + tx * 4) = o0;
        *(float4*)(Cp + 64 + tx * 4) = o1;
        ns0[i] = o0.x * o0.x + o0.y * o0.y + o0.z * o0.z + o0.w * o0.w;
        ns1[i] = o1.x * o1.x + o1.y * o1.y + o1.z * o1.z + o1.w * o1.w;
    }

    if (nrm != nullptr && set == 0) {
        #pragma unroll
        for (int i = 0; i < 8; i++) {
            #pragma unroll
            for (int off = 8; off > 0; off >>= 1) {
                ns0[i] += __shfl_xor_sync(0xffffffffu, ns0[i], off);
                ns1[i] += __shfl_xor_sync(0xffffffffu, ns1[i], off);
            }
        }
        if (tx == 0) {
            const int h0 = (blockIdx.x & 7) * 2;
            #pragma unroll
            for (int i = 0; i < 8; i++) {
                int row = bm + ty * 8 + i;
                int b = row >> 11;
                int n = row & (NTOK - 1);
                nrm[((size_t)(b * HEADS + h0)) * NTOK + n]     = ns0[i] * CLOG2E;
                nrm[((size_t)(b * HEADS + h0 + 1)) * NTOK + n] = ns1[i] * CLOG2E;
            }
        }
    }
}

// ---------------------------------------------------------------------------
// Flash attention (k=q), f32x2, no online softmax.
// 128 threads (16 ty x 8 tx), 8i x 8j per thread.
// K and V tiles stored DUPLICATED ((x,x) pairs) with interleaved layout +
// XOR swizzle -> FFMA2 operands come straight from LDS.128, zero pack MOVs.
//   inner_off(c) = ((c&7)>>1)*32 + (c>>3)*4 + (c&1)*2
//   sw(r) = (((r>>2)&7)<<2) ^ ((r&1)<<4)
//   off(r,c) = r*DROW + (inner_off(c) ^ sw(r))
// Ps (permuted P) aliases the Ks region (Ks dead after QK; barrier added).
// ---------------------------------------------------------------------------
#define QSTR 132
#define DROW 136
#define PSTR 132

__device__ __forceinline__ int sw_of(int r) {
    return (((r >> 2) & 7) << 2) ^ ((r & 1) << 4);
}

__global__ __launch_bounds__(128, 2) void attn_kernel(
    const float* __restrict__ q, const float* __restrict__ v,
    const float* __restrict__ norms, float* __restrict__ ao)
{
    extern __shared__ float sm[];
    float* Qs  = sm;                   // [64 d][QSTR]   8448 fl
    float* KPs = Qs + 64 * QSTR;       // Ks-dup [64 d][DROW] -> later Ps [64][PSTR]
    float* Vs  = KPs + 64 * DROW;      // Vs-dup [64 j][DROW]  8704 fl
    float* kn  = Vs + 64 * DROW;       // [64]

    const int tid = threadIdx.x;
    const int tx = tid & 7;            // j/d-group (8 x 8)
    const int ty = tid >> 3;           // i-group (16 x 8)
    const int tx4 = tx * 4;
    const int i0 = blockIdx.x * 128;
    const int bh = blockIdx.y;
    const int h = bh & (HEADS - 1);
    const int b = bh >> 4;

    const float* qb = q + (size_t)b * NTOK * INNER + h * DH;
    const float* vb = v + (size_t)b * NTOK * INNER + h * DH;
    const float* nb = norms + (size_t)bh * NTOK;

    // Q tile transposed: Qs[d][i] (natural pairs over i)
    #pragma unroll
    for (int it = 0; it < 16; it++) {
        int idx = tid + it * 128;
        int r = idx >> 4;
        int d = (idx & 15) * 4;
        float4 t = *(const float4*)(qb + (size_t)(i0 + r) * INNER + d);
        Qs[(d + 0) * QSTR + r] = t.x;
        Qs[(d + 1) * QSTR + r] = t.y;
        Qs[(d + 2) * QSTR + r] = t.z;
        Qs[(d + 3) * QSTR + r] = t.w;
    }

    float aaC[8], lsum[8];
    #pragma unroll
    for (int r = 0; r < 8; r++) {
        aaC[r] = __ldg(nb + i0 + ty * 8 + r);
        lsum[r] = 0.f;
    }

    u64 acco[4][8];
    #pragma unroll
    for (int ip = 0; ip < 4; ip++)
        #pragma unroll
        for (int c = 0; c < 8; c++) acco[ip][c] = 0ull;

    for (int j0 = 0; j0 < NTOK; j0 += 64) {
        __syncthreads();   // prev-tile PV reads (KPs/Vs) done; Q store fenced

        // Load K (transposed, duplicated) and V (duplicated) tiles
        #pragma unroll
        for (int it = 0; it < 8; it++) {
            int idx = tid + it * 128;
            int rj = idx >> 4;                 // j row 0..63
            int dbase = (idx & 15) * 4;
            float4 kt = *(const float4*)(qb + (size_t)(j0 + rj) * INNER + dbase);
            float4 vt = *(const float4*)(vb + (size_t)(j0 + rj) * INNER + dbase);
            float kv[4] = {kt.x, kt.y, kt.z, kt.w};
            float vv[4] = {vt.x, vt.y, vt.z, vt.w};
            int ioj = ((rj & 7) >> 1) * 32 + (rj >> 3) * 4 + ((rj & 1) << 1);
            int swr = sw_of(rj);
            #pragma unroll
            for (int e = 0; e < 4; e++) {
                int d = dbase + e;
                // K dup: outer = d, col = rj
                int offk = d * DROW + (ioj ^ sw_of(d));
                *(float2*)&KPs[offk] = make_float2(kv[e], kv[e]);
                // V dup: outer = rj, col = d
                int iod = (((d & 7) >> 1) << 5) + ((d >> 3) << 2) + ((e & 1) << 1);
                int offv = rj * DROW + (iod ^ swr);
                *(float2*)&Vs[offv] = make_float2(vv[e], vv[e]);
            }
        }
        if (tid < 64) kn[tid] = nb[j0 + tid];
        __syncthreads();

        // ---- S = Q @ K^T : per-thread 8i(pairs) x 8j, K-dup operands ----
        u64 accs[4][8];
        #pragma unroll
        for (int ip = 0; ip < 4; ip++)
            #pragma unroll
            for (int c = 0; c < 8; c++) accs[ip][c] = 0ull;

        #pragma unroll 8
        for (int kk = 0; kk < 64; kk++) {
            alignas(16) u64 a2[4];
            *(float4*)&a2[0] = *(const float4*)&Qs[kk * QSTR + ty * 8];
            *(float4*)&a2[2] = *(const float4*)&Qs[kk * QSTR + ty * 8 + 4];
            const float* kb_ = KPs + kk * DROW + (tx4 ^ sw_of(kk));
            alignas(16) u64 b2[8];
            *(float4*)&b2[0] = *(const float4*)(kb_);
            *(float4*)&b2[2] = *(const float4*)(kb_ + 32);
            *(float4*)&b2[4] = *(const float4*)(kb_ + 64);
            *(float4*)&b2[6] = *(const float4*)(kb_ + 96);
            #pragma unroll
            for (int ip = 0; ip < 4; ip++)
                #pragma unroll
                for (int c = 0; c < 8; c++)
                    ffma2(accs[ip][c], a2[ip], b2[c]);
        }

        // ---- p = exp2(qk*2C - aaC - bbC); plain l accumulation ----
        float bbC[8];
        #pragma unroll
        for (int c = 0; c < 8; c++) bbC[c] = kn[tx * 8 + c];

        float p[8][8];
        #pragma unroll
        for (int ip = 0; ip < 4; ip++) {
            const float a0 = aaC[2 * ip], a1 = aaC[2 * ip + 1];
            #pragma unroll
            for (int c = 0; c < 8; c++) {
                float2 t = unpack2(accs[ip][c]);
                float p0 = exp2f(fmaf(t.x, TWO_C, -a0) - bbC[c]);
                float p1 = exp2f(fmaf(t.y, TWO_C, -a1) - bbC[c]);
                p[2 * ip][c] = p0;
                p[2 * ip + 1][c] = p1;
                lsum[2 * ip] += p0;
                lsum[2 * ip + 1] += p1;
            }
        }

        __syncthreads();   // all warps done reading Ks before Ps overwrites it

        // store P (aliased onto KPs) at permuted row r = c*8 + tx (j = tx*8+c)
        #pragma unroll
        for (int c = 0; c < 8; c++) {
            int r = c * 8 + tx;
            float4 p0 = make_float4(p[0][c], p[1][c], p[2][c], p[3][c]);
            float4 p1 = make_float4(p[4][c], p[5][c], p[6][c], p[7][c]);
            *(float4*)&KPs[r * PSTR + ty * 8] = p0;
            *(float4*)&KPs[r * PSTR + ty * 8 + 4] = p1;
        }
        __syncthreads();

        // ---- PV: P natural i-pairs, V-dup operands ----
        #pragma unroll 1
        for (int c2 = 0; c2 < 8; c2++) {
            #pragma unroll 4
            for (int t2 = 0; t2 < 8; t2++) {
                int r = c2 * 8 + t2;
                int j = t2 * 8 + c2;
                alignas(16) u64 p2[4];
                *(float4*)&p2[0] = *(const float4*)&KPs[r * PSTR + ty * 8];
                *(float4*)&p2[2] = *(const float4*)&KPs[r * PSTR + ty * 8 + 4];
                const float* vb_ = Vs + j * DROW + (tx4 ^ sw_of(j));
                alignas(16) u64 v2[8];
                *(float4*)&v2[0] = *(const float4*)(vb_);
                *(float4*)&v2[2] = *(const float4*)(vb_ + 32);
                *(float4*)&v2[4] = *(const float4*)(vb_ + 64);
                *(float4*)&v2[6] = *(const float4*)(vb_ + 96);
                #pragma unroll
                for (int ip = 0; ip < 4; ip++)
                    #pragma unroll
                    for (int c = 0; c < 8; c++)
                        ffma2(acco[ip][c], p2[ip], v2[c]);
            }
        }
    }

    // final l reduction over the 8 tx lanes
    float inv[8];
    #pragma unroll
    for (int r = 0; r < 8; r++) {
        float lv = lsum[r];
        #pragma unroll
        for (int off = 4; off > 0; off >>= 1)
            lv += __shfl_xor_sync(0xffffffffu, lv, off);
        inv[r] = 1.f / lv;
    }

    // epilogue: rows ty*8 + 2ip + {0,1}, cols tx*8 .. +7
    float* ob = ao + ((size_t)b * NTOK + i0) * INNER + h * DH;
    #pragma unroll
    for (int ip = 0; ip < 4; ip++) {
        float2 o[8];
        #pragma unroll
        for (int c = 0; c < 8; c++) o[c] = unpack2(acco[ip][c]);
        int r0 = ty * 8 + 2 * ip;
        float inv0 = inv[2 * ip];
        float inv1 = inv[2 * ip + 1];
        float4 w00 = make_float4(o[0].x * inv0, o[1].x * inv0, o[2].x * inv0, o[3].x * inv0);
        float4 w01 = make_float4(o[4].x * inv0, o[5].x * inv0, o[6].x * inv0, o[7].x * inv0);
        float4 w10 = make_float4(o[0].y * inv1, o[1].y * inv1, o[2].y * inv1, o[3].y * inv1);
        float4 w11 = make_float4(o[4].y * inv1, o[5].y * inv1, o[6].y * inv1, o[7].y * inv1);
        *(float4*)(ob + (size_t)r0 * INNER + tx * 8) = w00;
        *(float4*)(ob + (size_t)r0 * INNER + tx * 8 + 4) = w01;
        *(float4*)(ob + (size_t)(r0 + 1) * INNER + tx * 8) = w10;
        *(float4*)(ob + (size_t)(r0 + 1) * INNER + tx * 8 + 4) = w11;
    }
}

// ---------------------------------------------------------------------------
extern "C" void kernel_launch(void* const* d_in, const int* in_sizes, int n_in,
                              void* d_out, int out_size)
{
    const float* x  = (const float*)d_in[0];
    const float* Wq = (const float*)d_in[1];
    const float* bq = (const float*)d_in[2];
    const float* Wv = (const float*)d_in[3];
    const float* bv = (const float*)d_in[4];
    const float* Wo = (const float*)d_in[5];
    const float* bo = (const float*)d_in[6];
    float* out = (float*)d_out;

    float *qp, *vp, *aop, *np;
    cudaGetSymbolAddress((void**)&qp,  g_q);
    cudaGetSymbolAddress((void**)&vp,  g_v);
    cudaGetSymbolAddress((void**)&aop, g_ao);
    cudaGetSymbolAddress((void**)&np,  g_norm);

    const int M = BATCH * NTOK;   // 8192

    // fused q+v projection (norms fused into q epilogue)
    sgemm_dual<<<dim3(16, M / 128), 256>>>(
        x, Wq, bq, qp, Wv, bv, vp, np, M, INNER, DMODEL);

    int smem = (64 * QSTR + 64 * DROW + 64 * DROW + 64) * (int)sizeof(float);
    cudaFuncSetAttribute(attn_kernel,
                         cudaFuncAttributeMaxDynamicSharedMemorySize, smem);
    attn_kernel<<<dim3(NTOK / 128, BATCH * HEADS), 128, smem>>>(qp, vp, np, aop);

    // output projection
    sgemm_dual<<<dim3(8, M / 128), 256>>>(
        aop, Wo, bo, out, Wo, bo, out, nullptr, M, DMODEL, INNER);
}

// round 17
// speedup vs baseline: 1.1274x; 1.1274x over previous
#include <cuda_runtime.h>
#include <math.h>

#define BATCH 4
#define NTOK  2048
#define DMODEL 1024
#define HEADS 16
#define DH    64
#define INNER 1024
#define SCALE 0.125f                 /* 64^-0.5 */
#define CLOG2E 0.1803368801111f      /* SCALE * log2(e) */
#define TWO_C  0.3606737602222f      /* 2 * SCALE * log2(e) */

typedef unsigned long long u64;

__device__ __forceinline__ u64 pack2(float x) {
    u64 r; asm("mov.b64 %0, {%1, %1};" : "=l"(r) : "f"(x)); return r;
}
__device__ __forceinline__ float2 unpack2(u64 a) {
    float2 f; asm("mov.b64 {%0, %1}, %2;" : "=f"(f.x), "=f"(f.y) : "l"(a)); return f;
}
__device__ __forceinline__ void ffma2(u64 &d, u64 a, u64 b) {
    asm("fma.rn.f32x2 %0, %1, %2, %0;" : "+l"(d) : "l"(a), "l"(b));
}
// raw MUFU.EX2 — avoids the accurate (multi-instruction) libm exp2f
__device__ __forceinline__ float ex2(float x) {
    float r; asm("ex2.approx.f32 %0, %1;" : "=f"(r) : "f"(x)); return r;
}

// Scratch (allocation-free rule: __device__ globals)
__device__ float g_q[BATCH * NTOK * INNER];
__device__ float g_v[BATCH * NTOK * INNER];
__device__ float g_ao[BATCH * NTOK * INNER];
__device__ float g_norm[BATCH * HEADS * NTOK];   // ‖q‖² * SCALE * log2e

// ---------------------------------------------------------------------------
// SGEMM (f32x2, BK=8, double-buffered, dual-output) — R14/R15-proven, frozen.
// ---------------------------------------------------------------------------
__global__ __launch_bounds__(256, 2) void sgemm_dual(
    const float* __restrict__ A,
    const float* __restrict__ W0, const float* __restrict__ b0, float* __restrict__ C0,
    const float* __restrict__ W1, const float* __restrict__ b1, float* __restrict__ C1,
    float* __restrict__ nrm,
    int M, int N, int K)
{
    __shared__ float As[2][8][128];
    __shared__ float Bs[2][8][128];

    const int tid = threadIdx.x;
    const int set = blockIdx.x >> 3;
    const int bn = (blockIdx.x & 7) * 128;
    const int bm = blockIdx.y * 128;
    const int tx = tid & 15;
    const int ty = tid >> 4;

    const float* W    = set ? W1 : W0;
    const float* bias = set ? b1 : b0;
    float*       C    = set ? C1 : C0;

    const int arow = tid >> 1;
    const int acol = (tid & 1) * 4;
    const int brow = tid >> 5;
    const int bcol = (tid & 31) * 4;

    const float* Ap = A + (size_t)(bm + arow) * K + acol;
    const float* Wp = W + (size_t)brow * N + bn + bcol;

    u64 acc[8][4];
    #pragma unroll
    for (int i = 0; i < 8; i++)
        #pragma unroll
        for (int j = 0; j < 4; j++) acc[i][j] = 0ull;

    {
        float4 a4 = *(const float4*)Ap;
        As[0][acol + 0][arow] = a4.x;
        As[0][acol + 1][arow] = a4.y;
        As[0][acol + 2][arow] = a4.z;
        As[0][acol + 3][arow] = a4.w;
        *(float4*)&Bs[0][brow][bcol] = *(const float4*)Wp;
    }
    __syncthreads();

    const int nst = K >> 3;
    for (int s = 0; s < nst; s++) {
        const int cur = s & 1;
        float4 na, nb;
        const bool more = (s + 1 < nst);
        if (more) {
            na = *(const float4*)(Ap + (s + 1) * 8);
            nb = *(const float4*)(Wp + (size_t)(s + 1) * 8 * N);
        }

        #pragma unroll
        for (int kk = 0; kk < 8; kk++) {
            float4 a0 = *(const float4*)&As[cur][kk][ty * 8];
            float4 a1 = *(const float4*)&As[cur][kk][ty * 8 + 4];
            alignas(16) u64 b2[4];
            *(float4*)&b2[0] = *(const float4*)&Bs[cur][kk][tx * 4];
            *(float4*)&b2[2] = *(const float4*)&Bs[cur][kk][64 + tx * 4];
            u64 ad[8];
            ad[0] = pack2(a0.x); ad[1] = pack2(a0.y);
            ad[2] = pack2(a0.z); ad[3] = pack2(a0.w);
            ad[4] = pack2(a1.x); ad[5] = pack2(a1.y);
            ad[6] = pack2(a1.z); ad[7] = pack2(a1.w);
            #pragma unroll
            for (int i = 0; i < 8; i++)
                #pragma unroll
                for (int j = 0; j < 4; j++)
                    ffma2(acc[i][j], ad[i], b2[j]);
        }

        if (more) {
            const int nxt = cur ^ 1;
            As[nxt][acol + 0][arow] = na.x;
            As[nxt][acol + 1][arow] = na.y;
            As[nxt][acol + 2][arow] = na.z;
            As[nxt][acol + 3][arow] = na.w;
            *(float4*)&Bs[nxt][brow][bcol] = nb;
            __syncthreads();
        }
    }

    float4 bb0 = *(const float4*)(bias + bn + tx * 4);
    float4 bb1 = *(const float4*)(bias + bn + 64 + tx * 4);

    float ns0[8], ns1[8];

    #pragma unroll
    for (int i = 0; i < 8; i++) {
        float* Cp = C + (size_t)(bm + ty * 8 + i) * N + bn;
        float2 p0 = unpack2(acc[i][0]), p1 = unpack2(acc[i][1]);
        float2 p2 = unpack2(acc[i][2]), p3 = unpack2(acc[i][3]);
        float4 o0 = make_float4(p0.x + bb0.x, p0.y + bb0.y, p1.x + bb0.z, p1.y + bb0.w);
        float4 o1 = make_float4(p2.x + bb1.x, p2.y + bb1.y, p3.x + bb1.z, p3.y + bb1.w);
        *(float4*)(Cp + tx * 4) = o0;
        *(float4*)(Cp + 64 + tx * 4) = o1;
        ns0[i] = o0.x * o0.x + o0.y * o0.y + o0.z * o0.z + o0.w * o0.w;
        ns1[i] = o1.x * o1.x + o1.y * o1.y + o1.z * o1.z + o1.w * o1.w;
    }

    if (nrm != nullptr && set == 0) {
        #pragma unroll
        for (int i = 0; i < 8; i++) {
            #pragma unroll
            for (int off = 8; off > 0; off >>= 1) {
                ns0[i] += __shfl_xor_sync(0xffffffffu, ns0[i], off);
                ns1[i] += __shfl_xor_sync(0xffffffffu, ns1[i], off);
            }
        }
        if (tx == 0) {
            const int h0 = (blockIdx.x & 7) * 2;
            #pragma unroll
            for (int i = 0; i < 8; i++) {
                int row = bm + ty * 8 + i;
                int b = row >> 11;
                int n = row & (NTOK - 1);
                nrm[((size_t)(b * HEADS + h0)) * NTOK + n]     = ns0[i] * CLOG2E;
                nrm[((size_t)(b * HEADS + h0 + 1)) * NTOK + n] = ns1[i] * CLOG2E;
            }
        }
    }
}

// ---------------------------------------------------------------------------
// Flash attention (k=q), f32x2, no online softmax — R15-proven layout
// (plain Qs/Ks/Vs/Ps, 128 threads, 8i x 8j), exp via raw MUFU.EX2.
// ---------------------------------------------------------------------------
#define QSTR 132
#define KSTR 68
#define VSTR 68
#define PSTR 132

__global__ __launch_bounds__(128, 2) void attn_kernel(
    const float* __restrict__ q, const float* __restrict__ v,
    const float* __restrict__ norms, float* __restrict__ ao)
{
    extern __shared__ float sm[];
    float* Qs = sm;                   // [64 d][132]  (128 i used)
    float* Ks = Qs + 64 * QSTR;       // [64 d][68]   (64 j used)
    float* Vs = Ks + 64 * KSTR;       // [64 j][68]   (64 d used)
    float* Ps = Vs + 64 * VSTR;       // [64 r][132]  (128 i used)
    float* kn = Ps + 64 * PSTR;       // [64]

    const int tid = threadIdx.x;
    const int tx = tid & 7;           // j-group (8 cols x 8)
    const int ty = tid >> 3;          // i-group (16 rows x 8)
    const int i0 = blockIdx.x * 128;
    const int bh = blockIdx.y;
    const int h = bh & (HEADS - 1);
    const int b = bh >> 4;

    const float* qb = q + (size_t)b * NTOK * INNER + h * DH;
    const float* vb = v + (size_t)b * NTOK * INNER + h * DH;
    const float* nb = norms + (size_t)bh * NTOK;

    // Q tile transposed: Qs[d][i], 128 rows x 64 d
    #pragma unroll
    for (int it = 0; it < 16; it++) {
        int idx = tid + it * 128;
        int r = idx >> 4;
        int d = (idx & 15) * 4;
        float4 t = *(const float4*)(qb + (size_t)(i0 + r) * INNER + d);
        Qs[(d + 0) * QSTR + r] = t.x;
        Qs[(d + 1) * QSTR + r] = t.y;
        Qs[(d + 2) * QSTR + r] = t.z;
        Qs[(d + 3) * QSTR + r] = t.w;
    }

    float aaC[8], lsum[8];
    #pragma unroll
    for (int r = 0; r < 8; r++) {
        aaC[r] = __ldg(nb + i0 + ty * 8 + r);
        lsum[r] = 0.f;
    }

    u64 acco[4][8];
    #pragma unroll
    for (int ip = 0; ip < 4; ip++)
        #pragma unroll
        for (int c = 0; c < 8; c++) acco[ip][c] = 0ull;

    for (int j0 = 0; j0 < NTOK; j0 += 64) {
        __syncthreads();   // prev-tile PV reads done; Q store fenced

        #pragma unroll
        for (int it = 0; it < 8; it++) {
            int idx = tid + it * 128;
            int r = idx >> 4;
            int d = (idx & 15) * 4;
            float4 kt = *(const float4*)(qb + (size_t)(j0 + r) * INNER + d);
            Ks[(d + 0) * KSTR + r] = kt.x;
            Ks[(d + 1) * KSTR + r] = kt.y;
            Ks[(d + 2) * KSTR + r] = kt.z;
            Ks[(d + 3) * KSTR + r] = kt.w;
            float4 vt = *(const float4*)(vb + (size_t)(j0 + r) * INNER + d);
            *(float4*)&Vs[r * VSTR + d] = vt;
        }
        if (tid < 64) kn[tid] = nb[j0 + tid];
        __syncthreads();

        // ---- S = Q @ K^T : per-thread 8i(4 pairs) x 8j ----
        u64 accs[4][8];
        #pragma unroll
        for (int ip = 0; ip < 4; ip++)
            #pragma unroll
            for (int c = 0; c < 8; c++) accs[ip][c] = 0ull;

        #pragma unroll 4
        for (int kk = 0; kk < 64; kk++) {
            alignas(16) u64 a2[4];
            *(float4*)&a2[0] = *(const float4*)&Qs[kk * QSTR + ty * 8];
            *(float4*)&a2[2] = *(const float4*)&Qs[kk * QSTR + ty * 8 + 4];
            float4 k0 = *(const float4*)&Ks[kk * KSTR + tx * 8];
            float4 k1 = *(const float4*)&Ks[kk * KSTR + tx * 8 + 4];
            u64 b2[8];
            b2[0] = pack2(k0.x); b2[1] = pack2(k0.y);
            b2[2] = pack2(k0.z); b2[3] = pack2(k0.w);
            b2[4] = pack2(k1.x); b2[5] = pack2(k1.y);
            b2[6] = pack2(k1.z); b2[7] = pack2(k1.w);
            #pragma unroll
            for (int ip = 0; ip < 4; ip++)
                #pragma unroll
                for (int c = 0; c < 8; c++)
                    ffma2(accs[ip][c], a2[ip], b2[c]);
        }

        // ---- p = ex2(qk*2C - aaC - bbC) via MUFU; plain l accumulation ----
        float bbC[8];
        #pragma unroll
        for (int c = 0; c < 8; c++) bbC[c] = kn[tx * 8 + c];

        float p[8][8];
        #pragma unroll
        for (int ip = 0; ip < 4; ip++) {
            const float a0 = aaC[2 * ip], a1 = aaC[2 * ip + 1];
            #pragma unroll
            for (int c = 0; c < 8; c++) {
                float2 t = unpack2(accs[ip][c]);
                float p0 = ex2(fmaf(t.x, TWO_C, -a0) - bbC[c]);
                float p1 = ex2(fmaf(t.y, TWO_C, -a1) - bbC[c]);
                p[2 * ip][c] = p0;
                p[2 * ip + 1][c] = p1;
                lsum[2 * ip] += p0;
                lsum[2 * ip + 1] += p1;
            }
        }

        // store P at permuted row r = c*8 + tx  (j = tx*8 + c)
        #pragma unroll
        for (int c = 0; c < 8; c++) {
            int r = c * 8 + tx;
            float4 p0 = make_float4(p[0][c], p[1][c], p[2][c], p[3][c]);
            float4 p1 = make_float4(p[4][c], p[5][c], p[6][c], p[7][c]);
            *(float4*)&Ps[r * PSTR + ty * 8] = p0;
            *(float4*)&Ps[r * PSTR + ty * 8 + 4] = p1;
        }
        __syncthreads();

        // ---- PV: iterate permuted rows; r = c2*8 + t2 holds j = t2*8 + c2 ----
        #pragma unroll 1
        for (int c2 = 0; c2 < 8; c2++) {
            #pragma unroll 4
            for (int t2 = 0; t2 < 8; t2++) {
                int r = c2 * 8 + t2;
                int j = t2 * 8 + c2;
                alignas(16) u64 p2[4];
                *(float4*)&p2[0] = *(const float4*)&Ps[r * PSTR + ty * 8];
                *(float4*)&p2[2] = *(const float4*)&Ps[r * PSTR + ty * 8 + 4];
                float4 v0 = *(const float4*)&Vs[j * VSTR + tx * 8];
                float4 v1 = *(const float4*)&Vs[j * VSTR + tx * 8 + 4];
                u64 v2[8];
                v2[0] = pack2(v0.x); v2[1] = pack2(v0.y);
                v2[2] = pack2(v0.z); v2[3] = pack2(v0.w);
                v2[4] = pack2(v1.x); v2[5] = pack2(v1.y);
                v2[6] = pack2(v1.z); v2[7] = pack2(v1.w);
                #pragma unroll
                for (int ip = 0; ip < 4; ip++)
                    #pragma unroll
                    for (int c = 0; c < 8; c++)
                        ffma2(acco[ip][c], p2[ip], v2[c]);
            }
        }
    }

    // final l reduction over the 8 tx lanes
    float inv[8];
    #pragma unroll
    for (int r = 0; r < 8; r++) {
        float lv = lsum[r];
        #pragma unroll
        for (int off = 4; off > 0; off >>= 1)
            lv += __shfl_xor_sync(0xffffffffu, lv, off);
        inv[r] = 1.f / lv;
    }

    // epilogue: rows ty*8 + 2ip + {0,1}, cols tx*8 .. +7
    float* ob = ao + ((size_t)b * NTOK + i0) * INNER + h * DH;
    #pragma unroll
    for (int ip = 0; ip < 4; ip++) {
        float2 o[8];
        #pragma unroll
        for (int c = 0; c < 8; c++) o[c] = unpack2(acco[ip][c]);
        int r0 = ty * 8 + 2 * ip;
        float inv0 = inv[2 * ip];
        float inv1 = inv[2 * ip + 1];
        float4 w00 = make_float4(o[0].x * inv0, o[1].x * inv0, o[2].x * inv0, o[3].x * inv0);
        float4 w01 = make_float4(o[4].x * inv0, o[5].x * inv0, o[6].x * inv0, o[7].x * inv0);
        float4 w10 = make_float4(o[0].y * inv1, o[1].y * inv1, o[2].y * inv1, o[3].y * inv1);
        float4 w11 = make_float4(o[4].y * inv1, o[5].y * inv1, o[6].y * inv1, o[7].y * inv1);
        *(float4*)(ob + (size_t)r0 * INNER + tx * 8) = w00;
        *(float4*)(ob + (size_t)r0 * INNER + tx * 8 + 4) = w01;
        *(float4*)(ob + (size_t)(r0 + 1) * INNER + tx * 8) = w10;
        *(float4*)(ob + (size_t)(r0 + 1) * INNER + tx * 8 + 4) = w11;
    }
}

// ---------------------------------------------------------------------------
extern "C" void kernel_launch(void* const* d_in, const int* in_sizes, int n_in,
                              void* d_out, int out_size)
{
    const float* x  = (const float*)d_in[0];
    const float* Wq = (const float*)d_in[1];
    const float* bq = (const float*)d_in[2];
    const float* Wv = (const float*)d_in[3];
    const float* bv = (const float*)d_in[4];
    const float* Wo = (const float*)d_in[5];
    const float* bo = (const float*)d_in[6];
    float* out = (float*)d_out;

    float *qp, *vp, *aop, *np;
    cudaGetSymbolAddress((void**)&qp,  g_q);
    cudaGetSymbolAddress((void**)&vp,  g_v);
    cudaGetSymbolAddress((void**)&aop, g_ao);
    cudaGetSymbolAddress((void**)&np,  g_norm);

    const int M = BATCH * NTOK;   // 8192

    // fused q+v projection (norms fused into q epilogue)
    sgemm_dual<<<dim3(16, M / 128), 256>>>(
        x, Wq, bq, qp, Wv, bv, vp, np, M, INNER, DMODEL);

    int smem = (64 * QSTR + 64 * KSTR + 64 * VSTR + 64 * PSTR + 64) * (int)sizeof(float);
    cudaFuncSetAttribute(attn_kernel,
                         cudaFuncAttributeMaxDynamicSharedMemorySize, smem);
    attn_kernel<<<dim3(NTOK / 128, BATCH * HEADS), 128, smem>>>(qp, vp, np, aop);

    // output projection
    sgemm_dual<<<dim3(8, M / 128), 256>>>(
        aop, Wo, bo, out, Wo, bo, out, nullptr, M, DMODEL, INNER);
}